// round 1
// baseline (speedup 1.0000x reference)
#include <cuda_runtime.h>
#include <math.h>

#define CS 1024
#define NH 16
#define HD 64

// ---------------- scratch (static device globals; no runtime allocation) ----
__device__ float g_q[1024 * 1024];
__device__ float g_k[1024 * 1024];
__device__ float g_v[1024 * 1024];
__device__ float g_g[1024 * 1024];
__device__ float g_tmp[1024 * 1024];
__device__ float g_z[16 * 1024 * 1024];   // [h][i][j]

// ---------------- GEMM body: C[M,N] = A[M,K] * B[N,K]^T (+bias / sigmoid) ----
// MODE 0: plain, 1: +bias[n], 2: sigmoid
template <int BM, int BN, int TM, int TN, int MODE>
__device__ __forceinline__ void gemm_body(const float* __restrict__ A,
                                          const float* __restrict__ B,
                                          float* __restrict__ C,
                                          const float* __restrict__ bias,
                                          float* As, float* Bs,
                                          int bm0, int bn0) {
    const int tid = threadIdx.x;
    constexpr int TNX = BN / TN;            // threads along n
    const int tx = tid % TNX;
    const int ty = tid / TNX;

    float acc[TM][TN];
#pragma unroll
    for (int i = 0; i < TM; i++)
#pragma unroll
        for (int j = 0; j < TN; j++) acc[i][j] = 0.f;

    for (int k0 = 0; k0 < CS; k0 += 8) {
        __syncthreads();
        if (tid < BM * 2) {
            int row = tid >> 1, ko = (tid & 1) * 4;
            float4 v = *(const float4*)(A + (size_t)(bm0 + row) * CS + k0 + ko);
            As[(ko + 0) * BM + row] = v.x;
            As[(ko + 1) * BM + row] = v.y;
            As[(ko + 2) * BM + row] = v.z;
            As[(ko + 3) * BM + row] = v.w;
        }
        if (tid < BN * 2) {
            int row = tid >> 1, ko = (tid & 1) * 4;
            float4 v = *(const float4*)(B + (size_t)(bn0 + row) * CS + k0 + ko);
            Bs[(ko + 0) * BN + row] = v.x;
            Bs[(ko + 1) * BN + row] = v.y;
            Bs[(ko + 2) * BN + row] = v.z;
            Bs[(ko + 3) * BN + row] = v.w;
        }
        __syncthreads();
#pragma unroll
        for (int kk = 0; kk < 8; kk++) {
            float a[TM], b[TN];
#pragma unroll
            for (int i = 0; i < TM; i += 4)
                *(float4*)&a[i] = *(const float4*)&As[kk * BM + ty * TM + i];
            if constexpr (TN == 8) {
                // split-B fragment: two 16B chunks -> conflict-free LDS.128
                *(float4*)&b[0] = *(const float4*)&Bs[kk * BN + tx * 4];
                *(float4*)&b[4] = *(const float4*)&Bs[kk * BN + BN / 2 + tx * 4];
            } else {
                *(float4*)&b[0] = *(const float4*)&Bs[kk * BN + tx * TN];
            }
#pragma unroll
            for (int i = 0; i < TM; i++)
#pragma unroll
                for (int j = 0; j < TN; j++) acc[i][j] += a[i] * b[j];
        }
    }

#pragma unroll
    for (int i = 0; i < TM; i++) {
        size_t m = (size_t)(bm0 + ty * TM + i);
#pragma unroll
        for (int j = 0; j < TN; j++) {
            int n;
            if constexpr (TN == 8)
                n = bn0 + ((j < 4) ? (tx * 4 + j) : (BN / 2 + tx * 4 + (j - 4)));
            else
                n = bn0 + tx * TN + j;
            float v = acc[i][j];
            if constexpr (MODE == 1) v += bias[n];
            if constexpr (MODE == 2) v = 1.f / (1.f + __expf(-v));
            C[m * CS + n] = v;
        }
    }
}

// ---------------- fused projections: q,k,v,g in one launch ------------------
__global__ __launch_bounds__(256) void proj_kernel(const float* __restrict__ s,
                                                   const float* __restrict__ kin,
                                                   const float* __restrict__ Wq,
                                                   const float* __restrict__ bq,
                                                   const float* __restrict__ Wk,
                                                   const float* __restrict__ Wv,
                                                   const float* __restrict__ Wg) {
    __shared__ float As[8 * 128];
    __shared__ float Bs[8 * 128];
    const int bm0 = blockIdx.y * 128;
    const int bn0 = blockIdx.x * 128;
    switch (blockIdx.z) {
        case 0: gemm_body<128, 128, 8, 8, 1>(s,   Wq, g_q, bq,      As, Bs, bm0, bn0); break;
        case 1: gemm_body<128, 128, 8, 8, 0>(kin, Wk, g_k, nullptr, As, Bs, bm0, bn0); break;
        case 2: gemm_body<128, 128, 8, 8, 0>(kin, Wv, g_v, nullptr, As, Bs, bm0, bn0); break;
        default: gemm_body<128, 128, 8, 8, 2>(s,  Wg, g_g, nullptr, As, Bs, bm0, bn0); break;
    }
}

// ---------------- output GEMM: out = (g*o) @ Wo^T ---------------------------
__global__ __launch_bounds__(256) void out_kernel(const float* __restrict__ Wo,
                                                  float* __restrict__ out) {
    __shared__ float As[8 * 64];
    __shared__ float Bs[8 * 64];
    gemm_body<64, 64, 4, 4, 0>(g_tmp, Wo, out, nullptr, As, Bs,
                               blockIdx.y * 64, blockIdx.x * 64);
}

// ---------------- pair-bias projection z[h][i][j] + mask --------------------
// z = bias[i,j,:] @ Wz[:,h]  + (1-mask[j]) * (-1e6)
__global__ __launch_bounds__(64) void z_kernel(const float* __restrict__ bias,
                                               const float* __restrict__ Wz,
                                               const float* __restrict__ mask) {
    __shared__ float sb[64 * 132];     // 64 pairs x 128 (stride 132: bank-clean)
    __shared__ float swz[128 * 16];    // Wz [c][h]
    const int tid = threadIdx.x;
    const size_t p0 = (size_t)blockIdx.x * 64;

    for (int idx = tid; idx < 128 * 16; idx += 64) swz[idx] = Wz[idx];
#pragma unroll
    for (int u = 0; u < 32; u++) {
        int lin = tid + u * 64;          // float4 index within block tile
        int pr = lin >> 5;               // pair row (0..63)
        int pc = (lin & 31) << 2;        // float column
        float4 v = *(const float4*)(bias + ((p0 + pr) << 7) + pc);
        *(float4*)&sb[pr * 132 + pc] = v;
    }
    __syncthreads();

    const int hg = tid & 3;              // head group: h = hg*4 + q
    const int pg = tid >> 2;             // pair group: pairs pg + 16*i
    float acc[4][4];
#pragma unroll
    for (int i = 0; i < 4; i++)
#pragma unroll
        for (int q = 0; q < 4; q++) acc[i][q] = 0.f;

#pragma unroll 4
    for (int c = 0; c < 128; c++) {
        float w[4];
        *(float4*)w = *(const float4*)&swz[c * 16 + hg * 4];
#pragma unroll
        for (int i = 0; i < 4; i++) {
            float bv = sb[(pg + 16 * i) * 132 + c];
            acc[i][0] += bv * w[0];
            acc[i][1] += bv * w[1];
            acc[i][2] += bv * w[2];
            acc[i][3] += bv * w[3];
        }
    }

#pragma unroll
    for (int i = 0; i < 4; i++) {
        size_t pair = p0 + pg + 16 * i;
        int j = (int)(pair & 1023);
        float madd = (1.f - mask[j]) * (-1000000.f);
#pragma unroll
        for (int q = 0; q < 4; q++) {
            int hh = hg * 4 + q;
            g_z[(size_t)hh * 1048576 + pair] = acc[i][q] + madd;
        }
    }
}

// ---------------- flash attention + fused gating ----------------------------
// grid (16 i-blocks, 16 heads), 256 threads. BM=64 queries, BN=64 keys, D=64.
// Q/K in smem transposed [d][c] with XOR-(d>>2) swizzle of the 16B column
// group -> conflict-free transpose stores AND conflict-free float4 reads.
__global__ __launch_bounds__(256) void attn_kernel() {
    extern __shared__ float sm[];
    float* Qt = sm;                // 64*64  (swizzled, [d][r])
    float* Kt = sm + 4096;         // 64*64  (swizzled, [d][c])
    float* Vs = sm + 8192;         // 64*64  ([j][d], natural)
    float* Ps = sm + 12288;        // 64*68  ([r][j], pad 68)

    const int tid = threadIdx.x;
    const int tx = tid & 15;       // d-column group for O / key group for S
    const int ty = tid >> 4;       // query-row group
    const int h = blockIdx.y;
    const int i0 = blockIdx.x * 64;
    const int colbase = h * 64;

    // load Q transposed+swizzled
#pragma unroll
    for (int u = 0; u < 4; u++) {
        int lin = tid + u * 256;                 // float4 id 0..1023
        int r = lin >> 4;
        int d4 = lin & 15;
        float4 v = *(const float4*)(g_q + (size_t)(i0 + r) * CS + colbase + (d4 << 2));
        int grp = ((r >> 2) ^ d4) & 15;
        float* p = Qt + ((d4 << 2) << 6) + (grp << 2) + (r & 3);
        p[0] = v.x; p[64] = v.y; p[128] = v.z; p[192] = v.w;
    }

    float m[4], l[4], O[4][4];
#pragma unroll
    for (int i = 0; i < 4; i++) {
        m[i] = -1e30f; l[i] = 0.f;
#pragma unroll
        for (int j = 0; j < 4; j++) O[i][j] = 0.f;
    }

    for (int j0 = 0; j0 < 1024; j0 += 64) {
        __syncthreads();   // prior PV done before overwriting K/V/P
#pragma unroll
        for (int u = 0; u < 4; u++) {
            int lin = tid + u * 256;
            int r = lin >> 4;
            int d4 = lin & 15;
            float4 kv = *(const float4*)(g_k + (size_t)(j0 + r) * CS + colbase + (d4 << 2));
            int grp = ((r >> 2) ^ d4) & 15;
            float* p = Kt + ((d4 << 2) << 6) + (grp << 2) + (r & 3);
            p[0] = kv.x; p[64] = kv.y; p[128] = kv.z; p[192] = kv.w;
            float4 vv = *(const float4*)(g_v + (size_t)(j0 + r) * CS + colbase + (d4 << 2));
            *(float4*)&Vs[r * 64 + (d4 << 2)] = vv;
        }
        __syncthreads();

        // S = Q K^T  (64 x 64 tile, 4x4 per thread)
        float S[4][4];
#pragma unroll
        for (int i = 0; i < 4; i++)
#pragma unroll
            for (int j = 0; j < 4; j++) S[i][j] = 0.f;

#pragma unroll 4
        for (int dg = 0; dg < 16; dg++) {
            const int qg = ((ty ^ dg) & 15) << 2;
            const int kg = ((tx ^ dg) & 15) << 2;
#pragma unroll
            for (int e = 0; e < 4; e++) {
                int dd = dg * 4 + e;
                float qa[4], ka[4];
                *(float4*)qa = *(const float4*)&Qt[dd * 64 + qg];
                *(float4*)ka = *(const float4*)&Kt[dd * 64 + kg];
#pragma unroll
                for (int i = 0; i < 4; i++)
#pragma unroll
                    for (int j = 0; j < 4; j++) S[i][j] += qa[i] * ka[j];
            }
        }

        // scale + pair bias (mask already folded into z)
#pragma unroll
        for (int i = 0; i < 4; i++) {
            float4 zv = *(const float4*)(g_z + (size_t)h * 1048576 +
                                         (size_t)(i0 + ty * 4 + i) * 1024 + j0 + (tx << 2));
            S[i][0] = S[i][0] * 0.125f + zv.x;
            S[i][1] = S[i][1] * 0.125f + zv.y;
            S[i][2] = S[i][2] * 0.125f + zv.z;
            S[i][3] = S[i][3] * 0.125f + zv.w;
        }

        // online softmax (row stats reduced across the 16 tx lanes)
#pragma unroll
        for (int i = 0; i < 4; i++) {
            float mx = fmaxf(fmaxf(S[i][0], S[i][1]), fmaxf(S[i][2], S[i][3]));
            mx = fmaxf(mx, __shfl_xor_sync(0xffffffffu, mx, 1));
            mx = fmaxf(mx, __shfl_xor_sync(0xffffffffu, mx, 2));
            mx = fmaxf(mx, __shfl_xor_sync(0xffffffffu, mx, 4));
            mx = fmaxf(mx, __shfl_xor_sync(0xffffffffu, mx, 8));
            float mnew = fmaxf(m[i], mx);
            float corr = __expf(m[i] - mnew);
            float rs = 0.f;
#pragma unroll
            for (int j = 0; j < 4; j++) {
                float p = __expf(S[i][j] - mnew);
                S[i][j] = p;
                rs += p;
            }
            rs += __shfl_xor_sync(0xffffffffu, rs, 1);
            rs += __shfl_xor_sync(0xffffffffu, rs, 2);
            rs += __shfl_xor_sync(0xffffffffu, rs, 4);
            rs += __shfl_xor_sync(0xffffffffu, rs, 8);
            l[i] = l[i] * corr + rs;
            m[i] = mnew;
#pragma unroll
            for (int j = 0; j < 4; j++) O[i][j] *= corr;
        }

        // write P tile (natural layout, pad 68 -> broadcast-clean reads)
#pragma unroll
        for (int i = 0; i < 4; i++)
            *(float4*)&Ps[(ty * 4 + i) * 68 + (tx << 2)] =
                make_float4(S[i][0], S[i][1], S[i][2], S[i][3]);
        __syncthreads();

        // O += P V
#pragma unroll 8
        for (int jj = 0; jj < 64; jj++) {
            float va[4];
            *(float4*)va = *(const float4*)&Vs[jj * 64 + (tx << 2)];
#pragma unroll
            for (int i = 0; i < 4; i++) {
                float p = Ps[(ty * 4 + i) * 68 + jj];
                O[i][0] += p * va[0];
                O[i][1] += p * va[1];
                O[i][2] += p * va[2];
                O[i][3] += p * va[3];
            }
        }
    }

    // epilogue: normalize + fuse gating multiply
#pragma unroll
    for (int i = 0; i < 4; i++) {
        float inv = 1.f / l[i];
        size_t idx = (size_t)(i0 + ty * 4 + i) * CS + colbase + (tx << 2);
        float4 gg = *(const float4*)(g_g + idx);
        float4 o;
        o.x = O[i][0] * inv * gg.x;
        o.y = O[i][1] * inv * gg.y;
        o.z = O[i][2] * inv * gg.z;
        o.w = O[i][3] * inv * gg.w;
        *(float4*)(g_tmp + idx) = o;
    }
}

// ---------------- launch ----------------------------------------------------
extern "C" void kernel_launch(void* const* d_in, const int* in_sizes, int n_in,
                              void* d_out, int out_size) {
    const float* s    = (const float*)d_in[0];
    const float* kin  = (const float*)d_in[1];
    const float* mask = (const float*)d_in[2];
    const float* bias = (const float*)d_in[3];
    const float* Wq   = (const float*)d_in[4];
    const float* bq   = (const float*)d_in[5];
    const float* Wk   = (const float*)d_in[6];
    const float* Wv   = (const float*)d_in[7];
    const float* Wg   = (const float*)d_in[8];
    const float* Wo   = (const float*)d_in[9];
    const float* Wz   = (const float*)d_in[10];
    // d_in[11] = multiplicity (must be 1 with B=1; repeat is a no-op)
    float* out = (float*)d_out;

    // 66560 B dynamic smem for attention (Qt+Kt+Vs 48KB + Ps 17408B).
    // Not a stream op -> graph-capture safe; idempotent per call.
    cudaFuncSetAttribute(attn_kernel, cudaFuncAttributeMaxDynamicSharedMemorySize, 66560);

    proj_kernel<<<dim3(8, 8, 4), 256>>>(s, kin, Wq, bq, Wk, Wv, Wg);
    z_kernel<<<16384, 64>>>(bias, Wz, mask);
    attn_kernel<<<dim3(16, 16), 256, 66560>>>();
    out_kernel<<<dim3(16, 16), 256>>>(Wo, out);
}